// round 11
// baseline (speedup 1.0000x reference)
#include <cuda_runtime.h>
#include <cuda_bf16.h>
#include <cstdint>

#define D 128
#define MAXN 100000
#define MAXE 1600000
#define SCAN_TILE 1024
#define MAXB ((MAXN + SCAN_TILE - 1) / SCAN_TILE)   // 98

#define BLK_M 64
#define GEMM_SMEM_BYTES 65536     // A fragment-major: 32KB hi + 32KB lo

// ---- scratch ----
__device__ uint32_t g_WFH[32768];        // fragment-major split weights hi (2 layers)
__device__ uint32_t g_WFL[32768];
__device__ float4   g_h[MAXN * 32];      // layer-1 output (fp32)
__device__ int      g_cnt[MAXN];
__device__ int      g_off[MAXN + 1];
__device__ int      g_cur[MAXN];
__device__ int      g_bsum[MAXB + 1];
__device__ int      g_eidx[MAXE];
__device__ int      g_is64;

// ---------------- split helper ----------------
__device__ __forceinline__ void split_pack(float v0, float v1,
                                           uint32_t& hi, uint32_t& lo) {
    __nv_bfloat162 h = __floats2bfloat162_rn(v0, v1);
    float r0 = v0 - __bfloat162float(h.x);
    float r1 = v1 - __bfloat162float(h.y);
    __nv_bfloat162 l = __floats2bfloat162_rn(r0, r1);
    hi = *(uint32_t*)&h;
    lo = *(uint32_t*)&l;
}

// ---------------- dtype detection ----------------
__global__ void detect_kernel(const unsigned long long* __restrict__ ei, int E) {
    int n = E < 1024 ? E : 1024;
    int i = threadIdx.x;
    int big = (i < n && ei[i] > 0xFFFFFFFFULL) ? 1 : 0;
    int any = __syncthreads_or(big);
    if (threadIdx.x == 0) g_is64 = any ? 0 : 1;
}

// low-dword edge loads (indices are nonneg < 2^32, so int64 low word suffices)
__device__ __forceinline__ int edge_src(const int* p32, int E, int e, int is64, int N) {
    int s = is64 ? p32[(size_t)2 * e] : p32[e];
    return (s < 0) ? 0 : (s >= N ? N - 1 : s);
}
__device__ __forceinline__ int edge_dst(const int* p32, int E, int e, int is64, int N) {
    int d = is64 ? p32[(size_t)2 * (E + e)] : p32[(size_t)E + e];
    return (d < 0) ? 0 : (d >= N ? N - 1 : d);
}

// ---------------- CSR build ----------------
__global__ void zero_cnt_kernel(int n) {
    int i = blockIdx.x * blockDim.x + threadIdx.x;
    if (i < n) g_cnt[i] = 0;
}

__global__ void count_kernel(const int* __restrict__ ei, int E, int N) {
    int e = blockIdx.x * blockDim.x + threadIdx.x;
    if (e < E) {
        int d = edge_dst(ei, E, e, g_is64, N);
        atomicAdd(&g_cnt[d], 1);
    }
}

__global__ void scan1_kernel(int n) {
    __shared__ int wsum[8];
    int t = threadIdx.x;
    int lane = t & 31, wid = t >> 5;
    int i0 = blockIdx.x * SCAN_TILE + t * 4;

    int a0 = 0, a1 = 0, a2 = 0, a3 = 0;
    if (i0 + 3 < n) {
        int4 v = *(const int4*)&g_cnt[i0];
        a0 = v.x; a1 = v.y; a2 = v.z; a3 = v.w;
    } else {
        if (i0     < n) a0 = g_cnt[i0];
        if (i0 + 1 < n) a1 = g_cnt[i0 + 1];
        if (i0 + 2 < n) a2 = g_cnt[i0 + 2];
        if (i0 + 3 < n) a3 = g_cnt[i0 + 3];
    }
    int s = a0 + a1 + a2 + a3;

    int x = s;
    #pragma unroll
    for (int o = 1; o < 32; o <<= 1) {
        int y = __shfl_up_sync(0xFFFFFFFFu, x, o);
        if (lane >= o) x += y;
    }
    if (lane == 31) wsum[wid] = x;
    __syncthreads();
    if (t < 8) {
        int w = wsum[t];
        #pragma unroll
        for (int o = 1; o < 8; o <<= 1) {
            int y = __shfl_up_sync(0xFFu, w, o);
            if (t >= o) w += y;
        }
        wsum[t] = w;
    }
    __syncthreads();
    int excl = x - s + (wid > 0 ? wsum[wid - 1] : 0);

    if (i0     < n) g_off[i0]     = excl;
    if (i0 + 1 < n) g_off[i0 + 1] = excl + a0;
    if (i0 + 2 < n) g_off[i0 + 2] = excl + a0 + a1;
    if (i0 + 3 < n) g_off[i0 + 3] = excl + a0 + a1 + a2;
    if (t == 0) g_bsum[blockIdx.x] = wsum[7];
}

__global__ void scan2_kernel(int B, int n) {
    __shared__ int sh[128];
    int t = threadIdx.x;
    int v = (t < B) ? g_bsum[t] : 0;
    sh[t] = v;
    __syncthreads();
    for (int o = 1; o < 128; o <<= 1) {
        int y = (t >= o) ? sh[t - o] : 0;
        __syncthreads();
        sh[t] += y;
        __syncthreads();
    }
    if (t < B) g_bsum[t] = sh[t] - v;
    if (t == 127) g_off[n] = sh[127];
}

__global__ void scan3_kernel(int n) {
    int i0 = blockIdx.x * SCAN_TILE + threadIdx.x * 4;
    int bp = g_bsum[blockIdx.x];
    #pragma unroll
    for (int j = 0; j < 4; j++) {
        int i = i0 + j;
        if (i < n) {
            int v = g_off[i] + bp;
            g_off[i] = v;
            g_cur[i] = v;
        }
    }
}

__global__ void fill_kernel(const int* __restrict__ ei, int E, int N) {
    int e = blockIdx.x * blockDim.x + threadIdx.x;
    if (e < E) {
        int is64 = g_is64;
        int s = edge_src(ei, E, e, is64, N);
        int d = edge_dst(ei, E, e, is64, N);
        int p = atomicAdd(&g_cur[d], 1);
        if (p >= 0 && p < MAXE) g_eidx[p] = s;
    }
}

// ---------------- precompute: fragment-major split weights ----------------
__global__ void wsplit_kernel(const float* __restrict__ Wl1, const float* __restrict__ Wr1,
                              const float* __restrict__ Wl2, const float* __restrict__ Wr2) {
    int i = blockIdx.x * blockDim.x + threadIdx.x;
    if (i >= 32768) return;
    int l = i >> 14;
    int r = i & 16383;
    int wn = r >> 12;
    int s = (r >> 8) & 15;
    int jh = (r >> 7) & 1;
    int lane = (r >> 2) & 31;
    int jj = r & 3;
    int nf = jh * 2 + (jj >> 1);
    int word = jj & 1;
    int n = wn * 32 + nf * 8 + (lane >> 2);
    int kk = s * 8 + (lane & 3) + word * 4;
    const float* W = (l == 0) ? (kk < 64 ? Wl1 : Wr1) : (kk < 64 ? Wl2 : Wr2);
    int k0 = (kk & 63) * 2;
    uint32_t hi, lo;
    split_pack(W[k0 * 128 + n], W[(k0 + 1) * 128 + n], hi, lo);
    g_WFH[i] = hi;
    g_WFL[i] = lo;
}

// ---------------- MMA helper ----------------
__device__ __forceinline__ void mma_bf16(float* c, const uint32_t* a, const uint32_t* b) {
    asm volatile(
        "mma.sync.aligned.m16n8k16.row.col.f32.bf16.bf16.f32 "
        "{%0,%1,%2,%3}, {%4,%5,%6,%7}, {%8,%9}, {%0,%1,%2,%3};"
        : "+f"(c[0]), "+f"(c[1]), "+f"(c[2]), "+f"(c[3])
        : "r"(a[0]), "r"(a[1]), "r"(a[2]), "r"(a[3]), "r"(b[0]), "r"(b[1]));
}

// fragment index for row r, kpair kk (0..127)
__device__ __forceinline__ int frag_idx(int r, int kk) {
    int wm = r >> 5;
    int mf = (r >> 4) & 1;
    int g = r & 7;
    int rbit = (r >> 3) & 1;
    int s = kk >> 3;
    int q = (((kk & 7) >= 4) ? 2 : 0) + rbit;
    int lt = g * 4 + (kk & 3);
    return ((wm * 16 + s) * 2 + mf) * 128 + lt * 4 + q;
}

// ---------------- fused aggregate + split-bf16 MMA SAGE layer ----------------
// out[m][:] = mean_{j in N(m)} root[j] @ Wl + root[m] @ Wr + b
// Each block: 64 rows. Warps gather+mean their 8 rows directly into the
// fragment-major smem A tile; root rows staged with inline split; then MMA.
__global__ void __launch_bounds__(256, 2)
gemm_fused_kernel(int layer, const float* __restrict__ xext,
                  const float* __restrict__ bias,
                  float* __restrict__ outF, int nrows) {
    extern __shared__ uint32_t sA[];   // hi [0,8192), lo [8192,16384)
    int tid = threadIdx.x;
    int lane = tid & 31;
    int warp = tid >> 5;
    int row0 = blockIdx.x * BLK_M;

    const float4* root = (layer == 0) ? (const float4*)xext : g_h;

    // ---- phase 1: gather + mean for this warp's 8 rows -> smem fragments ----
    for (int i = 0; i < 8; i++) {
        int r = warp * 8 + i;
        int gr = row0 + r;
        if (gr >= nrows) gr = nrows - 1;
        int beg = g_off[gr];
        int end = g_off[gr + 1];
        int cnt = end - beg;

        float4 acc = make_float4(0.f, 0.f, 0.f, 0.f);
        int e = beg;
        for (; e + 8 <= end; e += 8) {
            int s0 = g_eidx[e + 0];
            int s1 = g_eidx[e + 1];
            int s2 = g_eidx[e + 2];
            int s3 = g_eidx[e + 3];
            int s4 = g_eidx[e + 4];
            int s5 = g_eidx[e + 5];
            int s6 = g_eidx[e + 6];
            int s7 = g_eidx[e + 7];
            float4 v0 = root[(size_t)s0 * 32 + lane];
            float4 v1 = root[(size_t)s1 * 32 + lane];
            float4 v2 = root[(size_t)s2 * 32 + lane];
            float4 v3 = root[(size_t)s3 * 32 + lane];
            float4 v4 = root[(size_t)s4 * 32 + lane];
            float4 v5 = root[(size_t)s5 * 32 + lane];
            float4 v6 = root[(size_t)s6 * 32 + lane];
            float4 v7 = root[(size_t)s7 * 32 + lane];
            acc.x += ((v0.x + v1.x) + (v2.x + v3.x)) + ((v4.x + v5.x) + (v6.x + v7.x));
            acc.y += ((v0.y + v1.y) + (v2.y + v3.y)) + ((v4.y + v5.y) + (v6.y + v7.y));
            acc.z += ((v0.z + v1.z) + (v2.z + v3.z)) + ((v4.z + v5.z) + (v6.z + v7.z));
            acc.w += ((v0.w + v1.w) + (v2.w + v3.w)) + ((v4.w + v5.w) + (v6.w + v7.w));
        }
        for (; e < end; e++) {
            int s = g_eidx[e];
            float4 v = root[(size_t)s * 32 + lane];
            acc.x += v.x; acc.y += v.y; acc.z += v.z; acc.w += v.w;
        }
        float inv = 1.0f / fmaxf((float)cnt, 1.0f);
        acc.x *= inv; acc.y *= inv; acc.z *= inv; acc.w *= inv;

        // lane holds kpairs 2*lane (acc.x,acc.y) and 2*lane+1 (acc.z,acc.w)
        uint32_t h0, l0, h1, l1;
        split_pack(acc.x, acc.y, h0, l0);
        split_pack(acc.z, acc.w, h1, l1);
        int i0 = frag_idx(r, 2 * lane);
        int i1 = frag_idx(r, 2 * lane + 1);
        sA[i0] = h0; sA[8192 + i0] = l0;
        sA[i1] = h1; sA[8192 + i1] = l1;
    }

    // ---- phase 2: stage root rows (kpairs 64..127) with inline split ----
    for (int it = tid; it < 1024; it += 256) {
        int r = it >> 4;          // 0..63
        int c16 = it & 15;        // 0..15
        int gr = row0 + r;
        if (gr >= nrows) gr = nrows - 1;
        float4 f0 = root[(size_t)gr * 32 + c16 * 2];
        float4 f1 = root[(size_t)gr * 32 + c16 * 2 + 1];
        uint32_t hw[4], lw[4];
        split_pack(f0.x, f0.y, hw[0], lw[0]);
        split_pack(f0.z, f0.w, hw[1], lw[1]);
        split_pack(f1.x, f1.y, hw[2], lw[2]);
        split_pack(f1.z, f1.w, hw[3], lw[3]);
        #pragma unroll
        for (int w = 0; w < 4; w++) {
            int kk = 64 + c16 * 4 + w;
            int idx = frag_idx(r, kk);
            sA[idx] = hw[w];
            sA[8192 + idx] = lw[w];
        }
    }
    __syncthreads();

    // ---- phase 3: MMA mainloop ----
    int g = lane >> 2;
    int tig = lane & 3;
    int wm = warp & 1;
    int wn = warp >> 1;
    int m0 = wm * 32;
    int n0 = wn * 32;

    const uint4* sA4h = (const uint4*)sA;
    const uint4* sA4l = (const uint4*)(sA + 8192);
    const uint4* WFh = (const uint4*)g_WFH;
    const uint4* WFl = (const uint4*)g_WFL;
    int wbase = (layer * 4 + wn) * 1024;

    float acc[2][4][4];
    #pragma unroll
    for (int mf = 0; mf < 2; mf++)
        #pragma unroll
        for (int nf = 0; nf < 4; nf++)
            #pragma unroll
            for (int q = 0; q < 4; q++) acc[mf][nf][q] = 0.f;

    #pragma unroll 8
    for (int s = 0; s < 16; s++) {
        uint4 ah4[2], al4[2];
        #pragma unroll
        for (int mf = 0; mf < 2; mf++) {
            int ai = ((wm * 16 + s) * 2 + mf) * 32 + lane;
            ah4[mf] = sA4h[ai];
            al4[mf] = sA4l[ai];
        }
        int bi0 = wbase + s * 64 + lane;
        int bi1 = bi0 + 32;
        uint4 bh0 = __ldg(&WFh[bi0]);
        uint4 bh1 = __ldg(&WFh[bi1]);
        uint4 bl0 = __ldg(&WFl[bi0]);
        uint4 bl1 = __ldg(&WFl[bi1]);

        uint32_t bh[4][2] = {{bh0.x, bh0.y}, {bh0.z, bh0.w}, {bh1.x, bh1.y}, {bh1.z, bh1.w}};
        uint32_t bl[4][2] = {{bl0.x, bl0.y}, {bl0.z, bl0.w}, {bl1.x, bl1.y}, {bl1.z, bl1.w}};
        uint32_t ah[2][4] = {{ah4[0].x, ah4[0].y, ah4[0].z, ah4[0].w},
                             {ah4[1].x, ah4[1].y, ah4[1].z, ah4[1].w}};
        uint32_t al[2][4] = {{al4[0].x, al4[0].y, al4[0].z, al4[0].w},
                             {al4[1].x, al4[1].y, al4[1].z, al4[1].w}};

        #pragma unroll
        for (int mf = 0; mf < 2; mf++)
            #pragma unroll
            for (int nf = 0; nf < 4; nf++) {
                mma_bf16(acc[mf][nf], ah[mf], bh[nf]);
                mma_bf16(acc[mf][nf], ah[mf], bl[nf]);
                mma_bf16(acc[mf][nf], al[mf], bh[nf]);
            }
    }

    // ---- epilogue (fp32 out; layer 0 target is g_h) ----
    float* dst = (layer == 0) ? (float*)g_h : outF;
    #pragma unroll
    for (int nf = 0; nf < 4; nf++) {
        int col = n0 + nf * 8 + 2 * tig;
        float2 bv = *(const float2*)&bias[col];
        #pragma unroll
        for (int mf = 0; mf < 2; mf++) {
            int r0 = row0 + m0 + mf * 16 + g;
            int r1 = r0 + 8;
            if (r0 < nrows)
                *(float2*)&dst[(size_t)r0 * D + col] =
                    make_float2(acc[mf][nf][0] + bv.x, acc[mf][nf][1] + bv.y);
            if (r1 < nrows)
                *(float2*)&dst[(size_t)r1 * D + col] =
                    make_float2(acc[mf][nf][2] + bv.x, acc[mf][nf][3] + bv.y);
        }
    }
}

// ---------------- launch ----------------
extern "C" void kernel_launch(void* const* d_in, const int* in_sizes, int n_in,
                              void* d_out, int out_size) {
    const float* x  = (const float*)d_in[0];
    const int*   ei = (const int*)d_in[1];
    int off = n_in - 6;
    const float* Wl1 = (const float*)d_in[off + 0];
    const float* bl1 = (const float*)d_in[off + 1];
    const float* Wr1 = (const float*)d_in[off + 2];
    const float* Wl2 = (const float*)d_in[off + 3];
    const float* bl2 = (const float*)d_in[off + 4];
    const float* Wr2 = (const float*)d_in[off + 5];

    int N = in_sizes[0] / D;
    int E = in_sizes[1] / 2;
    int ORIGN = out_size / D;
    float* out = (float*)d_out;

    cudaFuncSetAttribute(gemm_fused_kernel,
                         cudaFuncAttributeMaxDynamicSharedMemorySize, GEMM_SMEM_BYTES);

    // ---- dtype detect + CSR build ----
    detect_kernel<<<1, 1024>>>((const unsigned long long*)ei, E);
    zero_cnt_kernel<<<(N + 255) / 256, 256>>>(N);
    count_kernel<<<(E + 255) / 256, 256>>>(ei, E, N);
    int B = (N + SCAN_TILE - 1) / SCAN_TILE;
    scan1_kernel<<<B, 256>>>(N);
    scan2_kernel<<<1, 128>>>(B, N);
    scan3_kernel<<<B, 256>>>(N);
    fill_kernel<<<(E + 255) / 256, 256>>>(ei, E, N);

    // ---- split weights ----
    wsplit_kernel<<<32768 / 256, 256>>>(Wl1, Wr1, Wl2, Wr2);

    int gemmGrid1 = (N + BLK_M - 1) / BLK_M;
    int gemmGrid2 = (ORIGN + BLK_M - 1) / BLK_M;

    // ---- layer 1: h = mean(x)@Wl1 + x@Wr1 + b1  (fused gather+GEMM) ----
    gemm_fused_kernel<<<gemmGrid1, 256, GEMM_SMEM_BYTES>>>(0, x, bl1, nullptr, N);

    // ---- layer 2: out = mean(h)@Wl2 + h@Wr2 + b2 ----
    gemm_fused_kernel<<<gemmGrid2, 256, GEMM_SMEM_BYTES>>>(1, nullptr, bl2, out, ORIGN);
}

// round 14
// speedup vs baseline: 1.3447x; 1.3447x over previous
#include <cuda_runtime.h>
#include <cuda_bf16.h>
#include <cstdint>

#define D 128
#define MAXN 100000
#define MAXE 1600000
#define SCAN_TILE 1024
#define MAXB ((MAXN + SCAN_TILE - 1) / SCAN_TILE)   // 98

#define BLK_M 64
#define GEMM_SMEM_BYTES 65536     // A fragment-major: 32KB hi + 32KB lo

// ---- scratch ----
__device__ uint32_t g_WFH[32768];        // fragment-major split weights hi (2 layers)
__device__ uint32_t g_WFL[32768];
__device__ uint4    g_mh4[MAXN * 16];    // mean split hi  [node][kpair/4]
__device__ uint4    g_ml4[MAXN * 16];
__device__ uint4    g_xh4[MAXN * 16];    // x split
__device__ uint4    g_xl4[MAXN * 16];
__device__ float4   g_h[MAXN * 32];      // layer-1 output (fp32)
__device__ int      g_cnt[MAXN];
__device__ int      g_off[MAXN + 1];
__device__ int      g_cur[MAXN];
__device__ int      g_bsum[MAXB + 1];
__device__ int      g_eidx[MAXE];
__device__ int      g_is64;

// ---------------- split helper ----------------
__device__ __forceinline__ void split_pack(float v0, float v1,
                                           uint32_t& hi, uint32_t& lo) {
    __nv_bfloat162 h = __floats2bfloat162_rn(v0, v1);
    float r0 = v0 - __bfloat162float(h.x);
    float r1 = v1 - __bfloat162float(h.y);
    __nv_bfloat162 l = __floats2bfloat162_rn(r0, r1);
    hi = *(uint32_t*)&h;
    lo = *(uint32_t*)&l;
}

// ---------------- dtype detection ----------------
__global__ void detect_kernel(const unsigned long long* __restrict__ ei, int E) {
    int n = E < 1024 ? E : 1024;
    int i = threadIdx.x;
    int big = (i < n && ei[i] > 0xFFFFFFFFULL) ? 1 : 0;
    int any = __syncthreads_or(big);
    if (threadIdx.x == 0) g_is64 = any ? 0 : 1;
}

// low-dword edge loads (indices nonneg < 2^32, so int64 low word suffices)
__device__ __forceinline__ int edge_src(const int* p32, int E, int e, int is64, int N) {
    int s = is64 ? p32[(size_t)2 * e] : p32[e];
    return (s < 0) ? 0 : (s >= N ? N - 1 : s);
}
__device__ __forceinline__ int edge_dst(const int* p32, int E, int e, int is64, int N) {
    int d = is64 ? p32[(size_t)2 * (E + e)] : p32[(size_t)E + e];
    return (d < 0) ? 0 : (d >= N ? N - 1 : d);
}

// ---------------- CSR build ----------------
__global__ void zero_cnt_kernel(int n) {
    int i = blockIdx.x * blockDim.x + threadIdx.x;
    if (i < n) g_cnt[i] = 0;
}

__global__ void count_kernel(const int* __restrict__ ei, int E, int N) {
    int e = blockIdx.x * blockDim.x + threadIdx.x;
    if (e < E) {
        int d = edge_dst(ei, E, e, g_is64, N);
        atomicAdd(&g_cnt[d], 1);
    }
}

__global__ void scan1_kernel(int n) {
    __shared__ int wsum[8];
    int t = threadIdx.x;
    int lane = t & 31, wid = t >> 5;
    int i0 = blockIdx.x * SCAN_TILE + t * 4;

    int a0 = 0, a1 = 0, a2 = 0, a3 = 0;
    if (i0 + 3 < n) {
        int4 v = *(const int4*)&g_cnt[i0];
        a0 = v.x; a1 = v.y; a2 = v.z; a3 = v.w;
    } else {
        if (i0     < n) a0 = g_cnt[i0];
        if (i0 + 1 < n) a1 = g_cnt[i0 + 1];
        if (i0 + 2 < n) a2 = g_cnt[i0 + 2];
        if (i0 + 3 < n) a3 = g_cnt[i0 + 3];
    }
    int s = a0 + a1 + a2 + a3;

    int x = s;
    #pragma unroll
    for (int o = 1; o < 32; o <<= 1) {
        int y = __shfl_up_sync(0xFFFFFFFFu, x, o);
        if (lane >= o) x += y;
    }
    if (lane == 31) wsum[wid] = x;
    __syncthreads();
    if (t < 8) {
        int w = wsum[t];
        #pragma unroll
        for (int o = 1; o < 8; o <<= 1) {
            int y = __shfl_up_sync(0xFFu, w, o);
            if (t >= o) w += y;
        }
        wsum[t] = w;
    }
    __syncthreads();
    int excl = x - s + (wid > 0 ? wsum[wid - 1] : 0);

    if (i0     < n) g_off[i0]     = excl;
    if (i0 + 1 < n) g_off[i0 + 1] = excl + a0;
    if (i0 + 2 < n) g_off[i0 + 2] = excl + a0 + a1;
    if (i0 + 3 < n) g_off[i0 + 3] = excl + a0 + a1 + a2;
    if (t == 0) g_bsum[blockIdx.x] = wsum[7];
}

__global__ void scan2_kernel(int B, int n) {
    __shared__ int sh[128];
    int t = threadIdx.x;
    int v = (t < B) ? g_bsum[t] : 0;
    sh[t] = v;
    __syncthreads();
    for (int o = 1; o < 128; o <<= 1) {
        int y = (t >= o) ? sh[t - o] : 0;
        __syncthreads();
        sh[t] += y;
        __syncthreads();
    }
    if (t < B) g_bsum[t] = sh[t] - v;
    if (t == 127) g_off[n] = sh[127];
}

__global__ void scan3_kernel(int n) {
    int i0 = blockIdx.x * SCAN_TILE + threadIdx.x * 4;
    int bp = g_bsum[blockIdx.x];
    #pragma unroll
    for (int j = 0; j < 4; j++) {
        int i = i0 + j;
        if (i < n) {
            int v = g_off[i] + bp;
            g_off[i] = v;
            g_cur[i] = v;
        }
    }
}

__global__ void fill_kernel(const int* __restrict__ ei, int E, int N) {
    int e = blockIdx.x * blockDim.x + threadIdx.x;
    if (e < E) {
        int is64 = g_is64;
        int s = edge_src(ei, E, e, is64, N);
        int d = edge_dst(ei, E, e, is64, N);
        int p = atomicAdd(&g_cur[d], 1);
        if (p >= 0 && p < MAXE) g_eidx[p] = s;
    }
}

// ---------------- precompute: fragment-major split weights ----------------
__global__ void wsplit_kernel(const float* __restrict__ Wl1, const float* __restrict__ Wr1,
                              const float* __restrict__ Wl2, const float* __restrict__ Wr2) {
    int i = blockIdx.x * blockDim.x + threadIdx.x;
    if (i >= 32768) return;
    int l = i >> 14;
    int r = i & 16383;
    int wn = r >> 12;
    int s = (r >> 8) & 15;
    int jh = (r >> 7) & 1;
    int lane = (r >> 2) & 31;
    int jj = r & 3;
    int nf = jh * 2 + (jj >> 1);
    int word = jj & 1;
    int n = wn * 32 + nf * 8 + (lane >> 2);
    int kk = s * 8 + (lane & 3) + word * 4;
    const float* W = (l == 0) ? (kk < 64 ? Wl1 : Wr1) : (kk < 64 ? Wl2 : Wr2);
    int k0 = (kk & 63) * 2;
    uint32_t hi, lo;
    split_pack(W[k0 * 128 + n], W[(k0 + 1) * 128 + n], hi, lo);
    g_WFH[i] = hi;
    g_WFL[i] = lo;
}

// ---------------- aggregation: warp per node -> split mean (+ own-row x split) ----
__global__ void aggregate_kernel(const float* __restrict__ xext, int split_own, int N) {
    int warp = (blockIdx.x * blockDim.x + threadIdx.x) >> 5;
    int lane = threadIdx.x & 31;
    if (warp >= N) return;
    const float4* feat = split_own ? (const float4*)xext : g_h;

    int beg = g_off[warp];
    int end = g_off[warp + 1];
    int cnt = end - beg;

    float4 acc = make_float4(0.f, 0.f, 0.f, 0.f);
    int e = beg;
    for (; e + 8 <= end; e += 8) {
        int s0 = g_eidx[e + 0];
        int s1 = g_eidx[e + 1];
        int s2 = g_eidx[e + 2];
        int s3 = g_eidx[e + 3];
        int s4 = g_eidx[e + 4];
        int s5 = g_eidx[e + 5];
        int s6 = g_eidx[e + 6];
        int s7 = g_eidx[e + 7];
        float4 v0 = feat[(size_t)s0 * 32 + lane];
        float4 v1 = feat[(size_t)s1 * 32 + lane];
        float4 v2 = feat[(size_t)s2 * 32 + lane];
        float4 v3 = feat[(size_t)s3 * 32 + lane];
        float4 v4 = feat[(size_t)s4 * 32 + lane];
        float4 v5 = feat[(size_t)s5 * 32 + lane];
        float4 v6 = feat[(size_t)s6 * 32 + lane];
        float4 v7 = feat[(size_t)s7 * 32 + lane];
        acc.x += ((v0.x + v1.x) + (v2.x + v3.x)) + ((v4.x + v5.x) + (v6.x + v7.x));
        acc.y += ((v0.y + v1.y) + (v2.y + v3.y)) + ((v4.y + v5.y) + (v6.y + v7.y));
        acc.z += ((v0.z + v1.z) + (v2.z + v3.z)) + ((v4.z + v5.z) + (v6.z + v7.z));
        acc.w += ((v0.w + v1.w) + (v2.w + v3.w)) + ((v4.w + v5.w) + (v6.w + v7.w));
    }
    for (; e < end; e++) {
        int s = g_eidx[e];
        float4 v = feat[(size_t)s * 32 + lane];
        acc.x += v.x; acc.y += v.y; acc.z += v.z; acc.w += v.w;
    }
    float inv = 1.0f / fmaxf((float)cnt, 1.0f);
    acc.x *= inv; acc.y *= inv; acc.z *= inv; acc.w *= inv;

    uint32_t h0, l0, h1, l1;
    split_pack(acc.x, acc.y, h0, l0);
    split_pack(acc.z, acc.w, h1, l1);
    ((uint2*)g_mh4)[(size_t)warp * 32 + lane] = make_uint2(h0, h1);
    ((uint2*)g_ml4)[(size_t)warp * 32 + lane] = make_uint2(l0, l1);

    if (split_own) {
        // split this node's own x row (L2-warm): lane covers kpairs 2*lane, 2*lane+1
        float4 v = feat[(size_t)warp * 32 + lane];
        uint32_t xh0, xl0, xh1, xl1;
        split_pack(v.x, v.y, xh0, xl0);
        split_pack(v.z, v.w, xh1, xl1);
        ((uint2*)g_xh4)[(size_t)warp * 32 + lane] = make_uint2(xh0, xh1);
        ((uint2*)g_xl4)[(size_t)warp * 32 + lane] = make_uint2(xl0, xl1);
    }
}

// ---------------- MMA helper ----------------
__device__ __forceinline__ void mma_bf16(float* c, const uint32_t* a, const uint32_t* b) {
    asm volatile(
        "mma.sync.aligned.m16n8k16.row.col.f32.bf16.bf16.f32 "
        "{%0,%1,%2,%3}, {%4,%5,%6,%7}, {%8,%9}, {%0,%1,%2,%3};"
        : "+f"(c[0]), "+f"(c[1]), "+f"(c[2]), "+f"(c[3])
        : "r"(a[0]), "r"(a[1]), "r"(a[2]), "r"(a[3]), "r"(b[0]), "r"(b[1]));
}

// ---------------- fragment-major split-bf16 fused SAGE GEMM ----------------
// out[m][:] = mean[m] @ Wl + root[m] @ Wr + b  (K=256 concat; 3 split products)
// layer 0: root = x (pre-split arrays), writes g_h fp32
// layer 1: root = h (fp32, split inline during staging), writes outF fp32
__global__ void __launch_bounds__(256)
gemm_frag_kernel(int layer, const float* __restrict__ bias,
                 float* __restrict__ outF, int nrows) {
    extern __shared__ uint32_t sA[];   // hi [0,8192), lo [8192,16384)
    int tid = threadIdx.x;
    int row0 = blockIdx.x * BLK_M;

    // ---- stage A tile fragment-major ----
    for (int it = tid; it < 2048; it += 256) {
        int r = it >> 5;          // 0..63
        int chunk = it & 31;      // 0..31 (kpair/4)
        int gr = row0 + r;
        if (gr >= nrows) gr = nrows - 1;
        uint32_t hw[4], lw[4];
        if (chunk < 16) {
            uint4 vh = g_mh4[(size_t)gr * 16 + chunk];
            uint4 vl = g_ml4[(size_t)gr * 16 + chunk];
            hw[0] = vh.x; hw[1] = vh.y; hw[2] = vh.z; hw[3] = vh.w;
            lw[0] = vl.x; lw[1] = vl.y; lw[2] = vl.z; lw[3] = vl.w;
        } else if (layer == 0) {
            uint4 vh = g_xh4[(size_t)gr * 16 + chunk - 16];
            uint4 vl = g_xl4[(size_t)gr * 16 + chunk - 16];
            hw[0] = vh.x; hw[1] = vh.y; hw[2] = vh.z; hw[3] = vh.w;
            lw[0] = vl.x; lw[1] = vl.y; lw[2] = vl.z; lw[3] = vl.w;
        } else {
            float4 f0 = g_h[(size_t)gr * 32 + (chunk - 16) * 2];
            float4 f1 = g_h[(size_t)gr * 32 + (chunk - 16) * 2 + 1];
            split_pack(f0.x, f0.y, hw[0], lw[0]);
            split_pack(f0.z, f0.w, hw[1], lw[1]);
            split_pack(f1.x, f1.y, hw[2], lw[2]);
            split_pack(f1.z, f1.w, hw[3], lw[3]);
        }
        int wm = r >> 5;
        int mf = (r >> 4) & 1;
        int g = r & 7;
        int rbit = (r >> 3) & 1;
        #pragma unroll
        for (int w = 0; w < 4; w++) {
            int kk = chunk * 4 + w;
            int s = kk >> 3;
            int q = (((kk & 7) >= 4) ? 2 : 0) + rbit;
            int lt = g * 4 + (kk & 3);
            int idx = ((wm * 16 + s) * 2 + mf) * 128 + lt * 4 + q;
            sA[idx] = hw[w];
            sA[8192 + idx] = lw[w];
        }
    }
    __syncthreads();

    int lane = tid & 31;
    int warp = tid >> 5;
    int g = lane >> 2;
    int tig = lane & 3;
    int wm = warp & 1;
    int wn = warp >> 1;
    int m0 = wm * 32;
    int n0 = wn * 32;

    const uint4* sA4h = (const uint4*)sA;
    const uint4* sA4l = (const uint4*)(sA + 8192);
    const uint4* WFh = (const uint4*)g_WFH;
    const uint4* WFl = (const uint4*)g_WFL;
    int wbase = (layer * 4 + wn) * 1024;

    float acc[2][4][4];
    #pragma unroll
    for (int mf = 0; mf < 2; mf++)
        #pragma unroll
        for (int nf = 0; nf < 4; nf++)
            #pragma unroll
            for (int q = 0; q < 4; q++) acc[mf][nf][q] = 0.f;

    #pragma unroll 8
    for (int s = 0; s < 16; s++) {
        uint4 ah4[2], al4[2];
        #pragma unroll
        for (int mf = 0; mf < 2; mf++) {
            int ai = ((wm * 16 + s) * 2 + mf) * 32 + lane;
            ah4[mf] = sA4h[ai];
            al4[mf] = sA4l[ai];
        }
        int bi0 = wbase + s * 64 + lane;
        int bi1 = bi0 + 32;
        uint4 bh0 = __ldg(&WFh[bi0]);
        uint4 bh1 = __ldg(&WFh[bi1]);
        uint4 bl0 = __ldg(&WFl[bi0]);
        uint4 bl1 = __ldg(&WFl[bi1]);

        uint32_t bh[4][2] = {{bh0.x, bh0.y}, {bh0.z, bh0.w}, {bh1.x, bh1.y}, {bh1.z, bh1.w}};
        uint32_t bl[4][2] = {{bl0.x, bl0.y}, {bl0.z, bl0.w}, {bl1.x, bl1.y}, {bl1.z, bl1.w}};
        uint32_t ah[2][4] = {{ah4[0].x, ah4[0].y, ah4[0].z, ah4[0].w},
                             {ah4[1].x, ah4[1].y, ah4[1].z, ah4[1].w}};
        uint32_t al[2][4] = {{al4[0].x, al4[0].y, al4[0].z, al4[0].w},
                             {al4[1].x, al4[1].y, al4[1].z, al4[1].w}};

        #pragma unroll
        for (int mf = 0; mf < 2; mf++)
            #pragma unroll
            for (int nf = 0; nf < 4; nf++) {
                mma_bf16(acc[mf][nf], ah[mf], bh[nf]);
                mma_bf16(acc[mf][nf], ah[mf], bl[nf]);
                mma_bf16(acc[mf][nf], al[mf], bh[nf]);
            }
    }

    // ---- epilogue (fp32 out; layer 0 target is g_h) ----
    float* dst = (layer == 0) ? (float*)g_h : outF;
    #pragma unroll
    for (int nf = 0; nf < 4; nf++) {
        int col = n0 + nf * 8 + 2 * tig;
        float2 bv = *(const float2*)&bias[col];
        #pragma unroll
        for (int mf = 0; mf < 2; mf++) {
            int r0 = row0 + m0 + mf * 16 + g;
            int r1 = r0 + 8;
            if (r0 < nrows)
                *(float2*)&dst[(size_t)r0 * D + col] =
                    make_float2(acc[mf][nf][0] + bv.x, acc[mf][nf][1] + bv.y);
            if (r1 < nrows)
                *(float2*)&dst[(size_t)r1 * D + col] =
                    make_float2(acc[mf][nf][2] + bv.x, acc[mf][nf][3] + bv.y);
        }
    }
}

// ---------------- launch ----------------
extern "C" void kernel_launch(void* const* d_in, const int* in_sizes, int n_in,
                              void* d_out, int out_size) {
    const float* x  = (const float*)d_in[0];
    const int*   ei = (const int*)d_in[1];
    int off = n_in - 6;
    const float* Wl1 = (const float*)d_in[off + 0];
    const float* bl1 = (const float*)d_in[off + 1];
    const float* Wr1 = (const float*)d_in[off + 2];
    const float* Wl2 = (const float*)d_in[off + 3];
    const float* bl2 = (const float*)d_in[off + 4];
    const float* Wr2 = (const float*)d_in[off + 5];

    int N = in_sizes[0] / D;
    int E = in_sizes[1] / 2;
    int ORIGN = out_size / D;
    float* out = (float*)d_out;

    cudaFuncSetAttribute(gemm_frag_kernel,
                         cudaFuncAttributeMaxDynamicSharedMemorySize, GEMM_SMEM_BYTES);

    // ---- dtype detect + CSR build ----
    detect_kernel<<<1, 1024>>>((const unsigned long long*)ei, E);
    zero_cnt_kernel<<<(N + 255) / 256, 256>>>(N);
    count_kernel<<<(E + 255) / 256, 256>>>(ei, E, N);
    int B = (N + SCAN_TILE - 1) / SCAN_TILE;
    scan1_kernel<<<B, 256>>>(N);
    scan2_kernel<<<1, 128>>>(B, N);
    scan3_kernel<<<B, 256>>>(N);
    fill_kernel<<<(E + 255) / 256, 256>>>(ei, E, N);

    // ---- split weights ----
    wsplit_kernel<<<32768 / 256, 256>>>(Wl1, Wr1, Wl2, Wr2);

    int gemmGrid1 = (N + BLK_M - 1) / BLK_M;
    int gemmGrid2 = (ORIGN + BLK_M - 1) / BLK_M;

    // ---- layer 1: mean(x)->split (+x own split) ; h = mean@Wl1 + x@Wr1 + b1 ----
    aggregate_kernel<<<(N * 32 + 255) / 256, 256>>>(x, 1, N);
    gemm_frag_kernel<<<gemmGrid1, 256, GEMM_SMEM_BYTES>>>(0, bl1, nullptr, N);

    // ---- layer 2: mean(h) only for output rows ; out = mean@Wl2 + h@Wr2 + b2 ----
    aggregate_kernel<<<(ORIGN * 32 + 255) / 256, 256>>>(nullptr, 0, ORIGN);
    gemm_frag_kernel<<<gemmGrid2, 256, GEMM_SMEM_BYTES>>>(1, bl2, out, ORIGN);
}